// round 2
// baseline (speedup 1.0000x reference)
#include <cuda_runtime.h>
#include <cuda_bf16.h>
#include <math.h>

#define D 256
#define VD 16
#define TM 32          // rows (nodes/edges) per CTA in GEMM kernels
#define TPAD 36        // padded row length (multiple of 4 for float4, odd-ish banks)
#define MAXN 50000
#define MAXE 400000
#define MAXG 256

// ---------------- scratch (static device allocations only) ----------------
__device__ float g_s   [MAXN * D];     // node scalar embedding
__device__ float g_vn  [MAXN * VD];    // vector-channel norms
__device__ float g_Pd  [MAXN * D];     // s @ Wm1[0:256] + bm1       (dst part)
__device__ float g_Qs  [MAXN * D];     // s @ Wm1[256:512] + vn @ Wm1[512:528]  (src part)
__device__ float g_agg [MAXN * D];     // scatter-sum of edge messages
__device__ float g_cnt [MAXN];         // in-degree
__device__ float g_WeF [17 * D];       // We[0:17] @ Wm1[528:784]
__device__ float g_beF [D];            // be @ Wm1[528:784]
__device__ float g_gsum[MAXG * D];
__device__ float g_gcnt[MAXG];

// ---------------- zero scratch that is accumulated into ----------------
__global__ void k_zero(int N, int G) {
    long long total = (long long)N * D + N + (long long)G * D + G;
    long long nd = (long long)N * D;
    long long gs0 = nd + N;
    long long gc0 = gs0 + (long long)G * D;
    for (long long i = (long long)blockIdx.x * blockDim.x + threadIdx.x;
         i < total; i += (long long)gridDim.x * blockDim.x) {
        if (i < nd)            g_agg[i] = 0.f;
        else if (i < gs0)      g_cnt[i - nd] = 0.f;
        else if (i < gc0)      g_gsum[i - gs0] = 0.f;
        else                   g_gcnt[i - gc0] = 0.f;
    }
}

// ---------------- fold edge embedding through Wm1 edge block ----------------
// block b < 17: WeF row b ;  block 17: beF
__global__ __launch_bounds__(D) void k_wef(const float* __restrict__ We,
                                           const float* __restrict__ be,
                                           const float* __restrict__ Wm1) {
    __shared__ float row[D];
    int j = threadIdx.x;
    int b = blockIdx.x;
    row[j] = (b < 17) ? We[b * D + j] : be[j];
    __syncthreads();
    float a = 0.f;
    #pragma unroll 4
    for (int c = 0; c < D; c++)
        a += row[c] * Wm1[(528 + c) * D + j];
    if (b < 17) g_WeF[b * D + j] = a;
    else        g_beF[j] = a;
}

// ---------------- node embeddings: s = node_s@Ws+bs ; v_norm ----------------
#define EMB_NODES 8
__global__ __launch_bounds__(D) void k_embed(const float* __restrict__ node_s,
                                             const float* __restrict__ node_v,
                                             const float* __restrict__ Ws,
                                             const float* __restrict__ bs,
                                             const float* __restrict__ Wv,
                                             const float* __restrict__ bv,
                                             int N) {
    __shared__ float sWs[23 * D];
    __shared__ float sbs[D];
    __shared__ float sWv[4 * VD];
    __shared__ float sbv[VD];
    __shared__ float ns[EMB_NODES][23];
    __shared__ float nv[EMB_NODES][12];
    int j = threadIdx.x;
    for (int i = j; i < 23 * D; i += D) sWs[i] = Ws[i];
    sbs[j] = bs[j];
    if (j < 4 * VD) sWv[j] = Wv[j];
    if (j < VD) sbv[j] = bv[j];

    int n0 = blockIdx.x * EMB_NODES;
    int nvld = min(EMB_NODES, N - n0);
    for (int i = j; i < nvld * 23; i += D) { int r = i / 23, k = i % 23; ns[r][k] = node_s[(n0 + r) * 23 + k]; }
    for (int i = j; i < nvld * 12; i += D) { int r = i / 12, k = i % 12; nv[r][k] = node_v[(n0 + r) * 12 + k]; }
    __syncthreads();

    for (int r = 0; r < nvld; r++) {
        float a = sbs[j];
        #pragma unroll
        for (int k = 0; k < 23; k++) a += ns[r][k] * sWs[k * D + j];
        g_s[(n0 + r) * D + j] = a;
        if (j < VD) {
            float x = sbv[j], y = sbv[j], z = sbv[j];
            #pragma unroll
            for (int k = 0; k < 4; k++) {
                float w = sWv[k * VD + j];
                x += nv[r][k * 3 + 0] * w;
                y += nv[r][k * 3 + 1] * w;
                z += nv[r][k * 3 + 2] * w;
            }
            g_vn[(n0 + r) * VD + j] = sqrtf(x * x + y * y + z * z);
        }
    }
}

// ---------------- per-node first-layer precompute: Pd, Qs ----------------
__global__ __launch_bounds__(D) void k_nodeP(const float* __restrict__ Wm1,
                                             const float* __restrict__ bm1,
                                             int N) {
    __shared__ float sT[D][TPAD];    // s tile, transposed [k][r]
    __shared__ float vT[VD][TPAD];
    int j = threadIdx.x;
    int n0 = blockIdx.x * TM;
    int nvld = min(TM, N - n0);

    for (int i = j; i < TM * D; i += D) {
        int r = i / D, k = i % D;
        sT[k][r] = (r < nvld) ? g_s[(n0 + r) * D + k] : 0.f;
    }
    for (int i = j; i < TM * VD; i += D) {
        int r = i / VD, k = i % VD;
        vT[k][r] = (r < nvld) ? g_vn[(n0 + r) * VD + k] : 0.f;
    }
    __syncthreads();

    float accP[TM], accQ[TM];
    float bm = bm1[j];
    #pragma unroll
    for (int r = 0; r < TM; r++) { accP[r] = bm; accQ[r] = 0.f; }

    for (int k = 0; k < D; k++) {
        float bP = Wm1[k * D + j];
        float bQ = Wm1[(256 + k) * D + j];
        const float4* row = (const float4*)&sT[k][0];
        #pragma unroll
        for (int r4 = 0; r4 < TM / 4; r4++) {
            float4 a = row[r4];
            accP[4*r4+0] += a.x * bP; accQ[4*r4+0] += a.x * bQ;
            accP[4*r4+1] += a.y * bP; accQ[4*r4+1] += a.y * bQ;
            accP[4*r4+2] += a.z * bP; accQ[4*r4+2] += a.z * bQ;
            accP[4*r4+3] += a.w * bP; accQ[4*r4+3] += a.w * bQ;
        }
    }
    #pragma unroll
    for (int k = 0; k < VD; k++) {
        float bQ = Wm1[(512 + k) * D + j];
        const float4* row = (const float4*)&vT[k][0];
        #pragma unroll
        for (int r4 = 0; r4 < TM / 4; r4++) {
            float4 a = row[r4];
            accQ[4*r4+0] += a.x * bQ;
            accQ[4*r4+1] += a.y * bQ;
            accQ[4*r4+2] += a.z * bQ;
            accQ[4*r4+3] += a.w * bQ;
        }
    }
    for (int r = 0; r < nvld; r++) {
        g_Pd[(n0 + r) * D + j] = accP[r];
        g_Qs[(n0 + r) * D + j] = accQ[r];
    }
}

// ---------------- edge kernel: hidden -> @Wm2 -> scatter ----------------
__global__ __launch_bounds__(D) void k_edge(const float* __restrict__ edge_s,
                                            const int* __restrict__ edge_index,
                                            const float* __restrict__ Wm2,
                                            const float* __restrict__ bm2,
                                            int E) {
    __shared__ float hT[D][TPAD];    // hidden tile transposed [k][r]
    __shared__ float es[TM * 17];
    __shared__ int ssrc[TM], sdst[TM];
    int j = threadIdx.x;
    int e0 = blockIdx.x * TM;
    int ev = min(TM, E - e0);

    if (j < TM) {
        int e = e0 + j;
        ssrc[j] = (j < ev) ? edge_index[e]     : 0;   // row 0 = src
        sdst[j] = (j < ev) ? edge_index[E + e] : 0;   // row 1 = dst
    }
    for (int i = j; i < TM * 17; i += D)
        es[i] = (i < ev * 17) ? edge_s[e0 * 17 + i] : 0.f;
    __syncthreads();

    // phase 1: hidden[r][j] = relu(Pd[dst][j] + Qs[src][j] + edge_s·WeF[:,j] + beF[j])
    float wf[17];
    #pragma unroll
    for (int k = 0; k < 17; k++) wf[k] = g_WeF[k * D + j];
    float bef = g_beF[j];
    for (int r = 0; r < TM; r++) {
        float h = bef + g_Pd[sdst[r] * D + j] + g_Qs[ssrc[r] * D + j];
        const float* er = &es[r * 17];
        #pragma unroll
        for (int k = 0; k < 17; k++) h += er[k] * wf[k];
        hT[j][r] = fmaxf(h, 0.f);
    }
    if (j < ev) atomicAdd(&g_cnt[sdst[j]], 1.f);
    __syncthreads();

    // phase 2: m = hidden @ Wm2 + bm2
    float acc[TM];
    float b2 = bm2[j];
    #pragma unroll
    for (int r = 0; r < TM; r++) acc[r] = b2;
    for (int k = 0; k < D; k++) {
        float b = Wm2[k * D + j];
        const float4* row = (const float4*)&hT[k][0];
        #pragma unroll
        for (int r4 = 0; r4 < TM / 4; r4++) {
            float4 a = row[r4];
            acc[4*r4+0] += a.x * b;
            acc[4*r4+1] += a.y * b;
            acc[4*r4+2] += a.z * b;
            acc[4*r4+3] += a.w * b;
        }
    }
    // phase 3: scatter
    for (int r = 0; r < ev; r++)
        atomicAdd(&g_agg[sdst[r] * D + j], acc[r]);
}

// ---------------- node update + MLP + LayerNorm + ReLU + pooling ----------------
__global__ __launch_bounds__(D) void k_node2(const float* __restrict__ Wn,
                                             const float* __restrict__ bn,
                                             const float* __restrict__ gamma,
                                             const float* __restrict__ beta,
                                             const int* __restrict__ batch,
                                             int N) {
    __shared__ float fT[(D + VD) * TPAD];  // feat tile transposed; reused as h scratch
    __shared__ float red[2][TM];           // mu, rstd per row
    __shared__ int sb[TM];
    int j = threadIdx.x;
    int n0 = blockIdx.x * TM;
    int nvld = min(TM, N - n0);

    for (int i = j; i < TM * D; i += D) {
        int r = i / D, k = i % D;
        float v = 0.f;
        if (r < nvld) {
            int n = n0 + r;
            v = g_s[n * D + k] + g_agg[n * D + k] / fmaxf(g_cnt[n], 1.f);
        }
        fT[k * TPAD + r] = v;
    }
    for (int i = j; i < TM * VD; i += D) {
        int r = i / VD, k = i % VD;
        fT[(D + k) * TPAD + r] = (r < nvld) ? g_vn[(n0 + r) * VD + k] : 0.f;
    }
    if (j < TM) sb[j] = (j < nvld) ? batch[n0 + j] : 0;
    __syncthreads();

    float acc[TM];
    float b = bn[j];
    #pragma unroll
    for (int r = 0; r < TM; r++) acc[r] = b;
    for (int k = 0; k < D + VD; k++) {
        float w = Wn[k * D + j];
        const float4* row = (const float4*)&fT[k * TPAD];
        #pragma unroll
        for (int r4 = 0; r4 < TM / 4; r4++) {
            float4 a = row[r4];
            acc[4*r4+0] += a.x * w;
            acc[4*r4+1] += a.y * w;
            acc[4*r4+2] += a.z * w;
            acc[4*r4+3] += a.w * w;
        }
    }
    __syncthreads();              // done reading fT; reuse as h matrix [TM][D]
    float* hS = fT;
    #pragma unroll
    for (int r = 0; r < TM; r++) hS[r * D + j] = acc[r];
    __syncthreads();

    int wid = j >> 5, lane = j & 31;
    for (int r = wid; r < TM; r += 8) {
        float s1 = 0.f, s2 = 0.f;
        #pragma unroll
        for (int c = lane; c < D; c += 32) { float x = hS[r * D + c]; s1 += x; s2 += x * x; }
        #pragma unroll
        for (int o = 16; o; o >>= 1) {
            s1 += __shfl_xor_sync(0xFFFFFFFFu, s1, o);
            s2 += __shfl_xor_sync(0xFFFFFFFFu, s2, o);
        }
        if (lane == 0) {
            float mu = s1 * (1.f / D);
            float var = s2 * (1.f / D) - mu * mu;
            red[0][r] = mu;
            red[1][r] = rsqrtf(var + 1e-5f);
        }
    }
    __syncthreads();

    float ga = gamma[j], be = beta[j];
    for (int r = 0; r < nvld; r++) {
        float v = (acc[r] - red[0][r]) * red[1][r] * ga + be;
        v = fmaxf(v, 0.f);
        atomicAdd(&g_gsum[sb[r] * D + j], v);
    }
    if (j < nvld) atomicAdd(&g_gcnt[sb[j]], 1.f);
}

// ---------------- final: divide pooled sums ----------------
__global__ __launch_bounds__(D) void k_final(float* __restrict__ out, int G) {
    int g = blockIdx.x, j = threadIdx.x;
    out[g * D + j] = g_gsum[g * D + j] / fmaxf(g_gcnt[g], 1.f);
}

// ---------------- launch ----------------
extern "C" void kernel_launch(void* const* d_in, const int* in_sizes, int n_in,
                              void* d_out, int out_size) {
    const float* node_s = (const float*)d_in[0];
    const float* node_v = (const float*)d_in[1];
    const float* edge_s = (const float*)d_in[2];
    const int*   edge_index = (const int*)d_in[3];
    const int*   batch  = (const int*)d_in[4];
    const float* Ws  = (const float*)d_in[5];
    const float* bs  = (const float*)d_in[6];
    const float* Wv  = (const float*)d_in[7];
    const float* bv  = (const float*)d_in[8];
    const float* We  = (const float*)d_in[9];
    const float* be  = (const float*)d_in[10];
    const float* Wm1 = (const float*)d_in[11];
    const float* bm1 = (const float*)d_in[12];
    const float* Wm2 = (const float*)d_in[13];
    const float* bm2 = (const float*)d_in[14];
    const float* Wn  = (const float*)d_in[15];
    const float* bn  = (const float*)d_in[16];
    const float* gamma = (const float*)d_in[17];
    const float* beta  = (const float*)d_in[18];

    int N = in_sizes[0] / 23;
    int E = in_sizes[2] / 17;
    int G = out_size / D;

    k_zero<<<1184, 256>>>(N, G);
    k_wef<<<18, D>>>(We, be, Wm1);
    k_embed<<<(N + EMB_NODES - 1) / EMB_NODES, D>>>(node_s, node_v, Ws, bs, Wv, bv, N);
    k_nodeP<<<(N + TM - 1) / TM, D>>>(Wm1, bm1, N);
    k_edge<<<(E + TM - 1) / TM, D>>>(edge_s, edge_index, Wm2, bm2, E);
    k_node2<<<(N + TM - 1) / TM, D>>>(Wn, bn, gamma, beta, batch, N);
    k_final<<<G, D>>>((float*)d_out, G);
}

// round 3
// speedup vs baseline: 3.7879x; 3.7879x over previous
#include <cuda_runtime.h>
#include <cuda_bf16.h>
#include <math.h>

#define D 256
#define VD 16
#define TM 32          // rows (nodes/edges) per CTA
#define TPAD 36        // padded row length for transposed SMEM tiles
#define MAXN 50000
#define MAXG 256

// ---------------- scratch ----------------
__device__ float g_vn  [MAXN * VD];    // vector-channel norms
__device__ float g_Pd  [MAXN * D];     // node_s @ (Ws@Wm1P) + bP   (dst part, incl bm1)
__device__ float g_Qs  [MAXN * D];     // node_s @ (Ws@Wm1Q) + vn @ Wm1V + bQ (src part)
__device__ float g_agg [MAXN * D];     // scatter-sum of relu(hidden)
__device__ float g_cnt [MAXN];         // in-degree
__device__ float g_WeF [17 * D];       // We[0:17] @ Wm1E
__device__ float g_beF [D];            // be @ Wm1E
__device__ float g_AP  [23 * D];       // Ws @ Wm1[0:256]
__device__ float g_AQ  [23 * D];       // Ws @ Wm1[256:512]
__device__ float g_bP  [D];            // bs @ Wm1P + bm1
__device__ float g_bQ  [D];            // bs @ Wm1Q
__device__ float g_AH  [23 * D];       // Ws @ Wn[0:256]
__device__ float g_WmF [D * D];        // Wm2 @ Wn[0:256]
__device__ float g_bH  [D];            // (bs+bm2) @ Wn[0:256] + bn
__device__ float g_gsum[MAXG * D];
__device__ float g_gcnt[MAXG];

// ---------------- zero accumulated buffers ----------------
__global__ void k_zero(int N, int G) {
    long long nd = (long long)N * D;
    long long gs0 = nd + N;
    long long gc0 = gs0 + (long long)G * D;
    long long total = gc0 + G;
    for (long long i = (long long)blockIdx.x * blockDim.x + threadIdx.x;
         i < total; i += (long long)gridDim.x * blockDim.x) {
        if (i < nd)            g_agg[i] = 0.f;
        else if (i < gs0)      g_cnt[i - nd] = 0.f;
        else if (i < gc0)      g_gsum[i - gs0] = 0.f;
        else                   g_gcnt[i - gc0] = 0.f;
    }
}

// ---------------- fold: edge embedding through Wm1 edge block ----------------
__global__ __launch_bounds__(D) void k_wef(const float* __restrict__ We,
                                           const float* __restrict__ be,
                                           const float* __restrict__ Wm1) {
    __shared__ float row[D];
    int j = threadIdx.x, b = blockIdx.x;
    row[j] = (b < 17) ? We[b * D + j] : be[j];
    __syncthreads();
    float a = 0.f;
    #pragma unroll 4
    for (int c = 0; c < D; c++) a += row[c] * Wm1[(528 + c) * D + j];
    if (b < 17) g_WeF[b * D + j] = a;
    else        g_beF[j] = a;
}

// ---------------- fold: Ws (and bs) through Wm1 P/Q blocks ----------------
__global__ __launch_bounds__(D) void k_fold2(const float* __restrict__ Ws,
                                             const float* __restrict__ bs,
                                             const float* __restrict__ Wm1,
                                             const float* __restrict__ bm1) {
    __shared__ float row[D];
    int j = threadIdx.x, b = blockIdx.x;   // b<23: Ws row b ; b==23: bs
    row[j] = (b < 23) ? Ws[b * D + j] : bs[j];
    __syncthreads();
    float aP = 0.f, aQ = 0.f;
    #pragma unroll 4
    for (int c = 0; c < D; c++) {
        float r = row[c];
        aP += r * Wm1[c * D + j];
        aQ += r * Wm1[(D + c) * D + j];
    }
    if (b < 23) { g_AP[b * D + j] = aP; g_AQ[b * D + j] = aQ; }
    else        { g_bP[j] = aP + bm1[j]; g_bQ[j] = aQ; }
}

// ---------------- fold: Wm2@WnS, Ws@WnS, bias ----------------
__global__ __launch_bounds__(D) void k_fold3(const float* __restrict__ Wm2,
                                             const float* __restrict__ bm2,
                                             const float* __restrict__ Ws,
                                             const float* __restrict__ bs,
                                             const float* __restrict__ Wn,
                                             const float* __restrict__ bn) {
    __shared__ float row[D];
    int j = threadIdx.x, b = blockIdx.x;
    if (b < D)            row[j] = Wm2[b * D + j];
    else if (b < D + 23)  row[j] = Ws[(b - D) * D + j];
    else                  row[j] = bs[j] + bm2[j];
    __syncthreads();
    float a = 0.f;
    #pragma unroll 4
    for (int c = 0; c < D; c++) a += row[c] * Wn[c * D + j];   // Wn[0:256] block
    if (b < D)            g_WmF[b * D + j] = a;
    else if (b < D + 23)  g_AH[(b - D) * D + j] = a;
    else                  g_bH[j] = a + bn[j];
}

// ---------------- node embed + first-layer precompute (K=23/16 GEMMs) ----------------
__global__ __launch_bounds__(D) void k_nodeEmb(const float* __restrict__ node_s,
                                               const float* __restrict__ node_v,
                                               const float* __restrict__ Wv,
                                               const float* __restrict__ bv,
                                               const float* __restrict__ Wm1,
                                               int N) {
    __shared__ float ns[TM][24];
    __shared__ float nv[TM][12];
    __shared__ float vnT[VD][TM + 4];
    __shared__ float sWv[4 * VD];
    __shared__ float sbv[VD];
    int j = threadIdx.x;
    int n0 = blockIdx.x * TM;
    int nvld = min(TM, N - n0);

    for (int i = j; i < nvld * 23; i += D) { ns[i / 23][i % 23] = node_s[n0 * 23 + i]; }
    for (int i = j; i < nvld * 12; i += D) { nv[i / 12][i % 12] = node_v[n0 * 12 + i]; }
    if (j < 4 * VD) sWv[j] = Wv[j];
    if (j < VD) sbv[j] = bv[j];
    __syncthreads();

    for (int idx = j; idx < TM * VD; idx += D) {
        int r = idx / VD, o = idx % VD;
        float val = 0.f;
        if (r < nvld) {
            float x = sbv[o], y = sbv[o], z = sbv[o];
            #pragma unroll
            for (int k = 0; k < 4; k++) {
                float w = sWv[k * VD + o];
                x += nv[r][k * 3 + 0] * w;
                y += nv[r][k * 3 + 1] * w;
                z += nv[r][k * 3 + 2] * w;
            }
            val = sqrtf(x * x + y * y + z * z);
            g_vn[(n0 + r) * VD + o] = val;
        }
        vnT[o][r] = val;
    }
    __syncthreads();

    float accP[TM], accQ[TM];
    float bp = g_bP[j], bq = g_bQ[j];
    #pragma unroll
    for (int r = 0; r < TM; r++) { accP[r] = bp; accQ[r] = bq; }

    #pragma unroll 4
    for (int k = 0; k < 23; k++) {
        float wP = __ldg(&g_AP[k * D + j]);
        float wQ = __ldg(&g_AQ[k * D + j]);
        #pragma unroll
        for (int r = 0; r < TM; r++) {
            float a = ns[r][k];
            accP[r] += a * wP;
            accQ[r] += a * wQ;
        }
    }
    const float* W1V = Wm1 + 512 * D;
    #pragma unroll 4
    for (int k = 0; k < VD; k++) {
        float wV = __ldg(&W1V[k * D + j]);
        #pragma unroll
        for (int r = 0; r < TM; r++) accQ[r] += vnT[k][r] * wV;
    }
    for (int r = 0; r < nvld; r++) {
        g_Pd[(n0 + r) * D + j] = accP[r];
        g_Qs[(n0 + r) * D + j] = accQ[r];
    }
}

// ---------------- edge kernel: hidden = relu(...) -> scatter into aggH ----------------
__global__ __launch_bounds__(D) void k_edge(const float* __restrict__ edge_s,
                                            const int* __restrict__ edge_index,
                                            int E) {
    __shared__ float es[TM][17];
    __shared__ int ssrc[TM], sdst[TM];
    int j = threadIdx.x;
    int e0 = blockIdx.x * TM;
    int ev = min(TM, E - e0);

    if (j < TM) {
        int e = e0 + min(j, ev - 1);
        ssrc[j] = edge_index[e];        // row 0 = src
        sdst[j] = edge_index[E + e];    // row 1 = dst
    }
    for (int i = j; i < ev * 17; i += D) es[i / 17][i % 17] = edge_s[e0 * 17 + i];
    __syncthreads();

    float wf[17];
    #pragma unroll
    for (int k = 0; k < 17; k++) wf[k] = g_WeF[k * D + j];
    float bef = g_beF[j];

    #pragma unroll 4
    for (int r = 0; r < TM; r++) {
        if (r >= ev) break;
        int d = sdst[r];
        float h = bef + __ldg(&g_Pd[d * D + j]) + __ldg(&g_Qs[ssrc[r] * D + j]);
        #pragma unroll
        for (int k = 0; k < 17; k++) h += es[r][k] * wf[k];
        h = fmaxf(h, 0.f);
        atomicAdd(&g_agg[d * D + j], h);
    }
    if (j < ev) atomicAdd(&g_cnt[sdst[j]], 1.f);
}

// ---------------- node output: 3 folded GEMMs + LayerNorm + ReLU + pooling ----------------
__global__ __launch_bounds__(D) void k_node2(const float* __restrict__ node_s,
                                             const float* __restrict__ Wn,
                                             const float* __restrict__ gamma,
                                             const float* __restrict__ beta,
                                             const int* __restrict__ batch,
                                             int N) {
    __shared__ float aT[D * TPAD];      // aggH tile transposed; reused as h scratch
    __shared__ float ns2[TM][24];
    __shared__ float vnT[VD][TPAD];
    __shared__ float rc[TM];
    __shared__ float red[2][TM];
    __shared__ int sb[TM];
    int j = threadIdx.x;
    int n0 = blockIdx.x * TM;
    int nvld = min(TM, N - n0);

    if (j < TM) {
        rc[j] = (j < nvld) ? 1.f / fmaxf(g_cnt[n0 + j], 1.f) : 0.f;
        sb[j] = (j < nvld) ? batch[n0 + j] : 0;
    }
    for (int i = j; i < nvld * 23; i += D) ns2[i / 23][i % 23] = node_s[n0 * 23 + i];
    for (int i = j; i < TM * VD; i += D) {
        int r = i / VD, k = i % VD;
        vnT[k][r] = (r < nvld) ? g_vn[(n0 + r) * VD + k] : 0.f;
    }
    __syncthreads();
    for (int i = j; i < TM * D; i += D) {
        int r = i >> 8, k = i & 255;
        aT[k * TPAD + r] = (r < nvld) ? g_agg[(n0 + r) * D + k] * rc[r] : 0.f;
    }
    __syncthreads();

    float acc[TM];
    float bh = g_bH[j];
    #pragma unroll
    for (int r = 0; r < TM; r++) acc[r] = bh;

    #pragma unroll 4
    for (int k = 0; k < 23; k++) {
        float w = __ldg(&g_AH[k * D + j]);
        #pragma unroll
        for (int r = 0; r < TM; r++) acc[r] += ns2[r][k] * w;
    }
    const float* WnV = Wn + D * D;
    #pragma unroll 4
    for (int k = 0; k < VD; k++) {
        float w = __ldg(&WnV[k * D + j]);
        const float4* row = (const float4*)&vnT[k][0];
        #pragma unroll
        for (int r4 = 0; r4 < TM / 4; r4++) {
            float4 a = row[r4];
            acc[4*r4+0] += a.x * w; acc[4*r4+1] += a.y * w;
            acc[4*r4+2] += a.z * w; acc[4*r4+3] += a.w * w;
        }
    }
    #pragma unroll 2
    for (int k = 0; k < D; k += 4) {
        float w0 = __ldg(&g_WmF[(k + 0) * D + j]);
        float w1 = __ldg(&g_WmF[(k + 1) * D + j]);
        float w2 = __ldg(&g_WmF[(k + 2) * D + j]);
        float w3 = __ldg(&g_WmF[(k + 3) * D + j]);
        const float4* r0 = (const float4*)&aT[(k + 0) * TPAD];
        const float4* r1 = (const float4*)&aT[(k + 1) * TPAD];
        const float4* r2 = (const float4*)&aT[(k + 2) * TPAD];
        const float4* r3 = (const float4*)&aT[(k + 3) * TPAD];
        #pragma unroll
        for (int r4 = 0; r4 < TM / 4; r4++) {
            float4 a0 = r0[r4], a1 = r1[r4], a2 = r2[r4], a3 = r3[r4];
            acc[4*r4+0] += a0.x * w0 + a1.x * w1 + a2.x * w2 + a3.x * w3;
            acc[4*r4+1] += a0.y * w0 + a1.y * w1 + a2.y * w2 + a3.y * w3;
            acc[4*r4+2] += a0.z * w0 + a1.z * w1 + a2.z * w2 + a3.z * w3;
            acc[4*r4+3] += a0.w * w0 + a1.w * w1 + a2.w * w2 + a3.w * w3;
        }
    }
    __syncthreads();                 // done reading aT; reuse as h [TM][D]
    float* hS = aT;
    #pragma unroll
    for (int r = 0; r < TM; r++) hS[r * D + j] = acc[r];
    __syncthreads();

    int wid = j >> 5, lane = j & 31;
    for (int r = wid; r < TM; r += 8) {
        float s1 = 0.f, s2 = 0.f;
        #pragma unroll
        for (int c = lane; c < D; c += 32) { float x = hS[r * D + c]; s1 += x; s2 += x * x; }
        #pragma unroll
        for (int o = 16; o; o >>= 1) {
            s1 += __shfl_xor_sync(0xFFFFFFFFu, s1, o);
            s2 += __shfl_xor_sync(0xFFFFFFFFu, s2, o);
        }
        if (lane == 0) {
            float mu = s1 * (1.f / D);
            float var = s2 * (1.f / D) - mu * mu;
            red[0][r] = mu;
            red[1][r] = rsqrtf(var + 1e-5f);
        }
    }
    __syncthreads();

    float ga = gamma[j], be = beta[j];
    for (int r = 0; r < nvld; r++) {
        float v = (acc[r] - red[0][r]) * red[1][r] * ga + be;
        v = fmaxf(v, 0.f);
        atomicAdd(&g_gsum[sb[r] * D + j], v);
    }
    if (j < nvld) atomicAdd(&g_gcnt[sb[j]], 1.f);
}

// ---------------- final: divide pooled sums ----------------
__global__ __launch_bounds__(D) void k_final(float* __restrict__ out, int G) {
    int g = blockIdx.x, j = threadIdx.x;
    out[g * D + j] = g_gsum[g * D + j] / fmaxf(g_gcnt[g], 1.f);
}

// ---------------- launch ----------------
extern "C" void kernel_launch(void* const* d_in, const int* in_sizes, int n_in,
                              void* d_out, int out_size) {
    const float* node_s = (const float*)d_in[0];
    const float* node_v = (const float*)d_in[1];
    const float* edge_s = (const float*)d_in[2];
    const int*   edge_index = (const int*)d_in[3];
    const int*   batch  = (const int*)d_in[4];
    const float* Ws  = (const float*)d_in[5];
    const float* bs  = (const float*)d_in[6];
    const float* Wv  = (const float*)d_in[7];
    const float* bv  = (const float*)d_in[8];
    const float* We  = (const float*)d_in[9];
    const float* be  = (const float*)d_in[10];
    const float* Wm1 = (const float*)d_in[11];
    const float* bm1 = (const float*)d_in[12];
    const float* Wm2 = (const float*)d_in[13];
    const float* bm2 = (const float*)d_in[14];
    const float* Wn  = (const float*)d_in[15];
    const float* bn  = (const float*)d_in[16];
    const float* gamma = (const float*)d_in[17];
    const float* beta  = (const float*)d_in[18];

    int N = in_sizes[0] / 23;
    int E = in_sizes[2] / 17;
    int G = out_size / D;

    k_zero<<<1184, 256>>>(N, G);
    k_wef<<<18, D>>>(We, be, Wm1);
    k_fold2<<<24, D>>>(Ws, bs, Wm1, bm1);
    k_fold3<<<D + 24, D>>>(Wm2, bm2, Ws, bs, Wn, bn);
    k_nodeEmb<<<(N + TM - 1) / TM, D>>>(node_s, node_v, Wv, bv, Wm1, N);
    k_edge<<<(E + TM - 1) / TM, D>>>(edge_s, edge_index, E);
    k_node2<<<(N + TM - 1) / TM, D>>>(node_s, Wn, gamma, beta, batch, N);
    k_final<<<G, D>>>((float*)d_out, G);
}